// round 4
// baseline (speedup 1.0000x reference)
#include <cuda_runtime.h>
#include <cuda_bf16.h>

// ArcSoftmaxLoss: loss = mean_b [ logsumexp_j(logits_bj) - logits_b,label_b ]
// logits = 64*costh, except logits[b,label] = 64*cos(acos(c_y)+0.5).
//
// Strategy: fixed-max LSE (M = 63.36 >= all logits since |costh|<0.99),
// unmodified row sum in the hot loop (pure streaming, no label check),
// label column fixed up once per row. exp via FMA-pipe 2^x polynomial
// (MUFU would be ~15x slower than the HBM floor).
//
// NOTE: label arrives as int32 (JAX default x64-disabled downcasts
// jnp.int64 -> int32; harness dtype set is {float32, int32, bfloat16}).

#define BATCH 512
#define NCLS  100000
#define NVEC  (NCLS / 4)          // 25000 float4 per row
#define THREADS 512

#define LOG2E 1.4426950408889634f
#define MMAX  63.36f              // 64 * 0.99
#define K1    (64.0f * LOG2E)     // multiply costh
#define K2    (-MMAX * LOG2E)     // subtract max (in log2 space)
#define COS_M 0.8775825618903728f // cos(0.5)
#define SIN_M 0.47942553860420300f// sin(0.5)

__device__ float g_row_loss[BATCH];

// 2^x for x in [-183, 0], branchless, FMA/ALU pipes only.
__device__ __forceinline__ float exp2_fast(float x) {
    x = fmaxf(x, -125.0f);                 // underflow guard (terms < 2^-125 irrelevant)
    float r  = x + 12582912.0f;            // round-to-nearest-int via 1.5*2^23
    float nf = r - 12582912.0f;
    float f  = x - nf;                     // f in [-0.5, 0.5]
    int   m  = __float_as_int(r) - 0x4B400000;  // the integer part
    float p = 1.33336e-3f;                 // Taylor coeffs of 2^f
    p = fmaf(p, f, 9.61813e-3f);
    p = fmaf(p, f, 5.550411e-2f);
    p = fmaf(p, f, 2.4022651e-1f);
    p = fmaf(p, f, 6.9314718e-1f);
    p = fmaf(p, f, 1.0f);
    return __int_as_float(__float_as_int(p) + (m << 23));  // p * 2^m
}

__global__ __launch_bounds__(THREADS)
void arc_row_kernel(const float* __restrict__ costh,
                    const int* __restrict__ label) {
    const int row = blockIdx.x;
    const float* rowp = costh + (size_t)row * NCLS;
    const float4* row4 = reinterpret_cast<const float4*>(rowp);

    float s0 = 0.f, s1 = 0.f, s2 = 0.f, s3 = 0.f;
    #pragma unroll 4
    for (int v = threadIdx.x; v < NVEC; v += THREADS) {
        float4 c = row4[v];
        s0 += exp2_fast(fmaf(c.x, K1, K2));
        s1 += exp2_fast(fmaf(c.y, K1, K2));
        s2 += exp2_fast(fmaf(c.z, K1, K2));
        s3 += exp2_fast(fmaf(c.w, K1, K2));
    }
    float s = (s0 + s1) + (s2 + s3);

    // warp reduce
    #pragma unroll
    for (int o = 16; o > 0; o >>= 1)
        s += __shfl_xor_sync(0xFFFFFFFFu, s, o);

    __shared__ float ws[THREADS / 32];
    const int wid = threadIdx.x >> 5;
    if ((threadIdx.x & 31) == 0) ws[wid] = s;
    __syncthreads();

    if (threadIdx.x == 0) {
        float tot = 0.f;
        #pragma unroll
        for (int i = 0; i < THREADS / 32; i++) tot += ws[i];

        // label fix-up: replace target column's contribution.
        // Clamp is a no-op for valid labels; guards against OOB gather.
        int lab = label[row];
        lab = max(0, min(lab, NCLS - 1));
        const float cy  = rowp[lab];
        float sn = sqrtf(fmaxf(1.0f - cy * cy, 0.0f));
        const float cym = cy * COS_M - sn * SIN_M;   // cos(acos(cy)+0.5)
        const float target = 64.0f * cym;

        tot = tot - exp2_fast(fmaf(cy,  K1, K2))
                  + exp2_fast(fmaf(cym, K1, K2));

        const float lse = MMAX + logf(tot);
        g_row_loss[row] = lse - target;
    }
}

__global__ __launch_bounds__(BATCH)
void arc_final_kernel(float* __restrict__ out) {
    float v = g_row_loss[threadIdx.x];
    #pragma unroll
    for (int o = 16; o > 0; o >>= 1)
        v += __shfl_xor_sync(0xFFFFFFFFu, v, o);

    __shared__ float ws[BATCH / 32];
    const int wid = threadIdx.x >> 5;
    if ((threadIdx.x & 31) == 0) ws[wid] = v;
    __syncthreads();

    if (threadIdx.x == 0) {
        float tot = 0.f;
        #pragma unroll
        for (int i = 0; i < BATCH / 32; i++) tot += ws[i];
        out[0] = tot * (1.0f / BATCH);
    }
}

extern "C" void kernel_launch(void* const* d_in, const int* in_sizes, int n_in,
                              void* d_out, int out_size) {
    const float* costh = (const float*)d_in[0];
    const int*   label = (const int*)d_in[1];
    float* out = (float*)d_out;

    arc_row_kernel<<<BATCH, THREADS>>>(costh, label);
    arc_final_kernel<<<1, BATCH>>>(out);
}